// round 4
// baseline (speedup 1.0000x reference)
#include <cuda_runtime.h>
#include <cuda_bf16.h>
#include <cstdint>

#define TOTAL_DIM 24976
#define NQ        97
#define THREADS   256

// ---- dynamic SMEM layout (bytes) ----
#define OFF_BIAS  0
#define OFF_GAMMA 2048
#define OFF_BETA  4096
#define OFF_SSUM  6144     // [64][8] f32
#define OFF_SSSQ  8192     // [64][8] f32
#define OFF_RST   10240    // [64][2] f32
#define OFF_A     10752    // 2 stages x 2 planes x 64 rows x 80B
#define A_STAGE   10240
#define A_PLANE   5120
#define A_ROWB    80
#define OFF_B     31232    // 2 stages x 2 planes x 32 rows x 1040B
#define B_STAGE   66560
#define B_PLANE   33280
#define B_ROWB    1040
#define SMEM_TOTAL 164352

// ---- prepped weights: bf16 hi/lo planes, [Kpad][512] ----
__device__ uint4 g_bh0[416 * 512 * 2 / 16], g_bl0[416 * 512 * 2 / 16];
__device__ uint4 g_bh1[256 * 512 * 2 / 16], g_bl1[256 * 512 * 2 / 16];
__device__ uint4 g_bh2[256 * 512 * 2 / 16], g_bl2[256 * 512 * 2 / 16];

__device__ __forceinline__ uint32_t smem_u32(const void* p) {
    uint32_t a;
    asm("{ .reg .u64 t; cvta.to.shared.u64 t, %1; cvt.u32.u64 %0, t; }" : "=r"(a) : "l"(p));
    return a;
}
#define LDSM_X4(r0, r1, r2, r3, a) \
    asm volatile("ldmatrix.sync.aligned.m8n8.x4.shared.b16 {%0,%1,%2,%3}, [%4];" \
                 : "=r"(r0), "=r"(r1), "=r"(r2), "=r"(r3) : "r"(a))
#define LDSM_X4T(r0, r1, r2, r3, a) \
    asm volatile("ldmatrix.sync.aligned.m8n8.x4.trans.shared.b16 {%0,%1,%2,%3}, [%4];" \
                 : "=r"(r0), "=r"(r1), "=r"(r2), "=r"(r3) : "r"(a))
#define MMA16816(c, a0, a1, a2, a3, b0, b1) \
    asm volatile("mma.sync.aligned.m16n8k16.row.col.f32.bf16.bf16.f32 " \
                 "{%0,%1,%2,%3}, {%4,%5,%6,%7}, {%8,%9}, {%0,%1,%2,%3};" \
                 : "+f"((c)[0]), "+f"((c)[1]), "+f"((c)[2]), "+f"((c)[3]) \
                 : "r"(a0), "r"(a1), "r"(a2), "r"(a3), "r"(b0), "r"(b1))
__device__ __forceinline__ void cp16(uint32_t dst, const void* src) {
    asm volatile("cp.async.cg.shared.global [%0], [%1], 16;" :: "r"(dst), "l"(src));
}
__device__ __forceinline__ void bf16_split(float v, uint16_t& h, uint16_t& l) {
    __nv_bfloat16 hb = __float2bfloat16_rn(v);
    __nv_bfloat16 lb = __float2bfloat16_rn(v - __bfloat162float(hb));
    h = *(uint16_t*)&hb; l = *(uint16_t*)&lb;
}

// ================= fused GEMM + bias + ReLU + LayerNorm =================
// CTA: 64 rows x 512 cols. 8 warps, warp tile 64 rows x 64 cols (wn = wid).
template <int KSPLIT, int LVALID, int NCHUNK, int SEGOFF, int QOFF>
__device__ __forceinline__ void run_split(const float* __restrict__ x,
                                          const float* __restrict__ bias_g,
                                          const float* __restrict__ gamma_g,
                                          const float* __restrict__ beta_g,
                                          float* __restrict__ out,
                                          const uint4* __restrict__ wbh,
                                          const uint4* __restrict__ wbl,
                                          int tile) {
    extern __shared__ char smem[];
    const uint32_t sb = smem_u32(smem);
    const int tid = threadIdx.x, lane = tid & 31, wn = tid >> 5;
    const int row0 = tile * 64;

    float* bias_s = (float*)(smem + OFF_BIAS);
    float* gam_s  = (float*)(smem + OFF_GAMMA);
    float* bet_s  = (float*)(smem + OFF_BETA);
    for (int i = tid; i < 512; i += THREADS) {
        bias_s[i] = bias_g[i]; gam_s[i] = gamma_g[i]; bet_s[i] = beta_g[i];
    }

    // per-thread x mapping: row tid>>2 (0..63), two float4 slots (tid&3, tid&3+4)
    const int xrow = tid >> 2, xs0 = tid & 3;
    const float* px;
    {
        int gr = row0 + xrow;
        int bb = gr / KSPLIT, jj = gr - bb * KSPLIT;
        px = x + (size_t)bb * TOTAL_DIM + SEGOFF + (size_t)jj * LVALID;
    }

    float acc[4][8][4];
#pragma unroll
    for (int mt = 0; mt < 4; mt++)
#pragma unroll
        for (int t = 0; t < 8; t++)
#pragma unroll
            for (int c = 0; c < 4; c++) acc[mt][t][c] = 0.f;

    const __nv_bfloat16* bh16 = (const __nv_bfloat16*)wbh;
    const __nv_bfloat16* bl16 = (const __nv_bfloat16*)wbl;

    // prologue: B chunk0 -> stage0 (8 cp16/plane/thread), x chunk0 -> regs
#pragma unroll
    for (int i = 0; i < 8; i++) {
        int fi = tid + i * THREADS;          // 0..2047
        int kr = fi >> 6, cc = fi & 63;
        cp16(sb + OFF_B + kr * B_ROWB + cc * 16, bh16 + (size_t)kr * 512 + cc * 8);
        cp16(sb + OFF_B + B_PLANE + kr * B_ROWB + cc * 16, bl16 + (size_t)kr * 512 + cc * 8);
    }
    asm volatile("cp.async.commit_group;" ::: "memory");

    float4 xv[2];
#pragma unroll
    for (int sl = 0; sl < 2; sl++) {
        int k0 = (xs0 + 4 * sl) * 4;
        xv[sl] = (LVALID % 32 == 0 || k0 + 4 <= LVALID) ? *(const float4*)(px + k0)
                                                        : make_float4(0.f, 0.f, 0.f, 0.f);
    }

    for (int c = 0; c < NCHUNK; c++) {
        const int s = c & 1;

        // STS A(c): split to bf16 hi/lo planes
#pragma unroll
        for (int sl = 0; sl < 2; sl++) {
            uint16_t h0, h1, h2, h3, l0, l1, l2, l3;
            bf16_split(xv[sl].x, h0, l0); bf16_split(xv[sl].y, h1, l1);
            bf16_split(xv[sl].z, h2, l2); bf16_split(xv[sl].w, h3, l3);
            uint2 ph = make_uint2((uint32_t)h0 | ((uint32_t)h1 << 16),
                                  (uint32_t)h2 | ((uint32_t)h3 << 16));
            uint2 pl = make_uint2((uint32_t)l0 | ((uint32_t)l1 << 16),
                                  (uint32_t)l2 | ((uint32_t)l3 << 16));
            uint32_t off = (uint32_t)(xrow * A_ROWB + (xs0 + 4 * sl) * 8);
            *(uint2*)(smem + OFF_A + s * A_STAGE + off) = ph;
            *(uint2*)(smem + OFF_A + s * A_STAGE + A_PLANE + off) = pl;
        }

        asm volatile("cp.async.wait_group 0;" ::: "memory");
        __syncthreads();

        // issue next chunk's loads
        if (c + 1 < NCHUNK) {
            const uint32_t bDst = sb + OFF_B + (s ^ 1) * B_STAGE;
            const size_t kbase = (size_t)(c + 1) * 32 * 512;
#pragma unroll
            for (int i = 0; i < 8; i++) {
                int fi = tid + i * THREADS;
                int kr = fi >> 6, cc = fi & 63;
                cp16(bDst + kr * B_ROWB + cc * 16, bh16 + kbase + (size_t)kr * 512 + cc * 8);
                cp16(bDst + B_PLANE + kr * B_ROWB + cc * 16, bl16 + kbase + (size_t)kr * 512 + cc * 8);
            }
            asm volatile("cp.async.commit_group;" ::: "memory");
#pragma unroll
            for (int sl = 0; sl < 2; sl++) {
                int k0 = (c + 1) * 32 + (xs0 + 4 * sl) * 4;
                xv[sl] = (LVALID % 32 == 0 || k0 + 4 <= LVALID)
                             ? *(const float4*)(px + k0) : make_float4(0.f, 0.f, 0.f, 0.f);
            }
        }

        // ---- compute stage s ----
        const uint32_t aH = sb + OFF_A + s * A_STAGE;
        const uint32_t aL = aH + A_PLANE;
        const uint32_t bH = sb + OFF_B + s * B_STAGE;
        const uint32_t bL = bH + B_PLANE;
#pragma unroll
        for (int ks = 0; ks < 2; ks++) {
            const uint32_t acol = (uint32_t)(((lane >> 4) << 3) + ks * 16);
            uint32_t ah[4][4], al[4][4];
#pragma unroll
            for (int mt = 0; mt < 4; mt++) {
                uint32_t aoff = (uint32_t)((mt * 16 + (lane & 15)) * A_ROWB) + acol * 2;
                LDSM_X4(ah[mt][0], ah[mt][1], ah[mt][2], ah[mt][3], aH + aoff);
                LDSM_X4(al[mt][0], al[mt][1], al[mt][2], al[mt][3], aL + aoff);
            }
            const uint32_t brow = (uint32_t)(ks * 16 + (lane & 15));
#pragma unroll
            for (int g = 0; g < 4; g++) {
                const uint32_t bcol = (uint32_t)(wn * 64 + g * 16 + ((lane >> 4) << 3));
                const uint32_t boff = brow * B_ROWB + bcol * 2;
                uint32_t b0, b1, b2, b3, c0, c1, c2, c3;
                LDSM_X4T(b0, b1, b2, b3, bH + boff);
                LDSM_X4T(c0, c1, c2, c3, bL + boff);
#pragma unroll
                for (int mt = 0; mt < 4; mt++) {
                    MMA16816(acc[mt][2 * g],     ah[mt][0], ah[mt][1], ah[mt][2], ah[mt][3], b0, b1);
                    MMA16816(acc[mt][2 * g + 1], ah[mt][0], ah[mt][1], ah[mt][2], ah[mt][3], b2, b3);
                    MMA16816(acc[mt][2 * g],     al[mt][0], al[mt][1], al[mt][2], al[mt][3], b0, b1);
                    MMA16816(acc[mt][2 * g + 1], al[mt][0], al[mt][1], al[mt][2], al[mt][3], b2, b3);
                    MMA16816(acc[mt][2 * g],     ah[mt][0], ah[mt][1], ah[mt][2], ah[mt][3], c0, c1);
                    MMA16816(acc[mt][2 * g + 1], ah[mt][0], ah[mt][1], ah[mt][2], ah[mt][3], c2, c3);
                }
            }
        }
    }

    // ================= epilogue: bias + ReLU + LN =================
    float* ssum = (float*)(smem + OFF_SSUM);
    float* sssq = (float*)(smem + OFF_SSSQ);
    float* rst  = (float*)(smem + OFF_RST);

#pragma unroll
    for (int mt = 0; mt < 4; mt++) {
        float sum0 = 0.f, ssq0 = 0.f, sum1 = 0.f, ssq1 = 0.f;
#pragma unroll
        for (int t = 0; t < 8; t++) {
            int cb = wn * 64 + t * 8 + (lane & 3) * 2;
            float b0v = bias_s[cb], b1v = bias_s[cb + 1];
            float h;
            h = fmaxf(acc[mt][t][0] + b0v, 0.f); acc[mt][t][0] = h; sum0 += h; ssq0 += h * h;
            h = fmaxf(acc[mt][t][1] + b1v, 0.f); acc[mt][t][1] = h; sum0 += h; ssq0 += h * h;
            h = fmaxf(acc[mt][t][2] + b0v, 0.f); acc[mt][t][2] = h; sum1 += h; ssq1 += h * h;
            h = fmaxf(acc[mt][t][3] + b1v, 0.f); acc[mt][t][3] = h; sum1 += h; ssq1 += h * h;
        }
#pragma unroll
        for (int o = 1; o <= 2; o <<= 1) {
            sum0 += __shfl_xor_sync(0xffffffffu, sum0, o);
            ssq0 += __shfl_xor_sync(0xffffffffu, ssq0, o);
            sum1 += __shfl_xor_sync(0xffffffffu, sum1, o);
            ssq1 += __shfl_xor_sync(0xffffffffu, ssq1, o);
        }
        if ((lane & 3) == 0) {
            int r0 = mt * 16 + (lane >> 2);
            ssum[r0 * 8 + wn] = sum0;       sssq[r0 * 8 + wn] = ssq0;
            ssum[(r0 + 8) * 8 + wn] = sum1; sssq[(r0 + 8) * 8 + wn] = ssq1;
        }
    }
    __syncthreads();
    if (tid < 64) {
        float s = 0.f, q = 0.f;
#pragma unroll
        for (int i = 0; i < 8; i++) { s += ssum[tid * 8 + i]; q += sssq[tid * 8 + i]; }
        float mean = s * (1.f / 512.f);
        float var  = q * (1.f / 512.f) - mean * mean;
        rst[tid * 2] = mean;
        rst[tid * 2 + 1] = rsqrtf(var + 1e-5f);
    }
    __syncthreads();

#pragma unroll
    for (int mt = 0; mt < 4; mt++) {
        int r0 = mt * 16 + (lane >> 2);
        float m0 = rst[r0 * 2], rs0 = rst[r0 * 2 + 1];
        float m1 = rst[(r0 + 8) * 2], rs1 = rst[(r0 + 8) * 2 + 1];
        int gr0 = row0 + r0, gr1 = gr0 + 8;
        int b0i = gr0 / KSPLIT, j0 = gr0 - b0i * KSPLIT;
        int b1i = gr1 / KSPLIT, j1 = gr1 - b1i * KSPLIT;
        float* o0 = out + ((size_t)b0i * NQ + QOFF + j0) * 512;
        float* o1 = out + ((size_t)b1i * NQ + QOFF + j1) * 512;
#pragma unroll
        for (int t = 0; t < 8; t++) {
            int cb = wn * 64 + t * 8 + (lane & 3) * 2;
            float g0 = gam_s[cb], g1 = gam_s[cb + 1];
            float e0 = bet_s[cb], e1 = bet_s[cb + 1];
            float2 v0 = make_float2((acc[mt][t][0] - m0) * rs0 * g0 + e0,
                                    (acc[mt][t][1] - m0) * rs0 * g1 + e1);
            float2 v1 = make_float2((acc[mt][t][2] - m1) * rs1 * g0 + e0,
                                    (acc[mt][t][3] - m1) * rs1 * g1 + e1);
            *(float2*)(o0 + cb) = v0;
            *(float2*)(o1 + cb) = v1;
        }
    }
}

__global__ void __launch_bounds__(THREADS, 1)
fused_kernel(const float* __restrict__ x,
             const float* b0, const float* g0, const float* be0,
             const float* b1, const float* g1, const float* be1,
             const float* b2, const float* g2, const float* be2,
             float* __restrict__ out) {
    const int blk = blockIdx.x;
    if (blk < 32)         run_split<1,  400, 13, 0,     0 >(x, b0, g0, be0, out, g_bh0, g_bl0, blk);
    else if (blk < 1952)  run_split<60, 256, 8,  400,   1 >(x, b1, g1, be1, out, g_bh1, g_bl1, blk - 32);
    else                  run_split<36, 256, 8,  15760, 61>(x, b2, g2, be2, out, g_bh2, g_bl2, blk - 1952);
}

// ================= weight prep: W f32 -> bf16 hi/lo planes =================
__device__ __forceinline__ void prep_one(const float* __restrict__ W, uint4* bh, uint4* bl,
                                         int Lvalid, int idx) {
    int k = idx >> 9, n = idx & 511;
    float v = (k < Lvalid) ? W[(size_t)k * 512 + n] : 0.f;
    uint16_t h, l;
    bf16_split(v, h, l);
    ((uint16_t*)bh)[idx] = h;
    ((uint16_t*)bl)[idx] = l;
}

__global__ void prep_kernel(const float* __restrict__ W0, const float* __restrict__ W1,
                            const float* __restrict__ W2) {
    const int idx = blockIdx.x * blockDim.x + threadIdx.x;
    const int T0 = 416 * 512, T1 = 256 * 512, T2 = 256 * 512;
    if (idx < T0)                prep_one(W0, g_bh0, g_bl0, 400, idx);
    else if (idx < T0 + T1)      prep_one(W1, g_bh1, g_bl1, 256, idx - T0);
    else if (idx < T0 + T1 + T2) prep_one(W2, g_bh2, g_bl2, 256, idx - T0 - T1);
}

// ================= launch =================
extern "C" void kernel_launch(void* const* d_in, const int* in_sizes, int n_in,
                              void* d_out, int out_size) {
    (void)in_sizes; (void)n_in; (void)out_size;
    const float* x = (const float*)d_in[0];
    float* out = (float*)d_out;

    cudaFuncSetAttribute(fused_kernel, cudaFuncAttributeMaxDynamicSharedMemorySize, SMEM_TOTAL);

    const int prep_total = (416 + 256 + 256) * 512;
    prep_kernel<<<(prep_total + 255) / 256, 256>>>(
        (const float*)d_in[1], (const float*)d_in[5], (const float*)d_in[9]);

    fused_kernel<<<3104, THREADS, SMEM_TOTAL>>>(
        x,
        (const float*)d_in[2],  (const float*)d_in[3],  (const float*)d_in[4],
        (const float*)d_in[6],  (const float*)d_in[7],  (const float*)d_in[8],
        (const float*)d_in[10], (const float*)d_in[11], (const float*)d_in[12],
        out);
}